// round 9
// baseline (speedup 1.0000x reference)
#include <cuda_runtime.h>
#include <cstdint>

// ---------------------------------------------------------------------------
// TimeMix collapses to: out = (sigmoid(xr @ Wr^T) * (xv @ Wv^T or wkv@t0)) @ Wo^T
// For t>0 padded state is zero so wkv == v; only 4 rows at t==0 need wkv.
// Engine: legacy mma.sync tf32 (tcgen05 unusable: harness targets compute_103).
// R8: CTA tile 128x256, warp tile 64x64 -> LDS per MMA drops 1.5x, tensor-bound.
// ---------------------------------------------------------------------------

namespace {
constexpr int  BDIM = 4;
constexpr int  TDIM = 2048;
constexpr int  CDIM = 2048;
constexpr long MDIM = (long)BDIM * TDIM;   // 8192
constexpr int  KDIM = CDIM;
constexpr int  NDIM = CDIM;

constexpr int BM = 128, BN = 256, BK = 32;
constexpr int LSTR = 36;                           // padded row stride (floats)
constexpr int MATA_FLOATS  = BM * LSTR;            // 4608
constexpr int MATB_FLOATS  = BN * LSTR;            // 9216
constexpr int STAGE_FLOATS = MATA_FLOATS + MATB_FLOATS;   // 13824
constexpr int NSTAGE = 3;
constexpr int DYN_SMEM = NSTAGE * STAGE_FLOATS * 4;       // 165888
constexpr int NKT = KDIM / BK;                     // 64
}

// Scratch (static device arrays — no cudaMalloc anywhere)
__device__ float g_xv[MDIM * KDIM];
__device__ float g_xr[MDIM * KDIM];
__device__ float g_v [MDIM * NDIM];
__device__ float g_rv[MDIM * NDIM];
__device__ float g_wv[(long)NDIM * KDIM];
__device__ float g_wr[(long)NDIM * KDIM];
__device__ float g_wo[(long)NDIM * KDIM];

__device__ __forceinline__ float rna_tf32(float f) {
    uint32_t u;
    asm("cvt.rna.tf32.f32 %0, %1;" : "=r"(u) : "f"(f));
    return __uint_as_float(u);
}
__device__ __forceinline__ void cp16(uint32_t s, const void* g) {
    asm volatile("cp.async.cg.shared.global [%0], [%1], 16;" :: "r"(s), "l"(g));
}

// ---- round live weights to tf32 (rna removes truncation bias)
__global__ void prep_w_kernel(const float* __restrict__ wv,
                              const float* __restrict__ wr,
                              const float* __restrict__ wo) {
    long i = ((long)blockIdx.x * blockDim.x + threadIdx.x) * 4;
    float4 a = *(const float4*)(wv + i);
    float4 b = *(const float4*)(wr + i);
    float4 c = *(const float4*)(wo + i);
    a.x = rna_tf32(a.x); a.y = rna_tf32(a.y); a.z = rna_tf32(a.z); a.w = rna_tf32(a.w);
    b.x = rna_tf32(b.x); b.y = rna_tf32(b.y); b.z = rna_tf32(b.z); b.w = rna_tf32(b.w);
    c.x = rna_tf32(c.x); c.y = rna_tf32(c.y); c.z = rna_tf32(c.z); c.w = rna_tf32(c.w);
    *(float4*)(g_wv + i) = a;
    *(float4*)(g_wr + i) = b;
    *(float4*)(g_wo + i) = c;
}

// ---- token-mix + tf32 rounding for the two live A-operands
__global__ void prep_x_kernel(const float* __restrict__ x,
                              const float* __restrict__ tmv,
                              const float* __restrict__ tmr,
                              const float* __restrict__ xxp) {
    long i = ((long)blockIdx.x * blockDim.x + threadIdx.x) * 4;
    int  c = (int)(i & (CDIM - 1));
    float4 xv = *(const float4*)(x   + i);
    float4 mv = *(const float4*)(tmv + c);
    float4 mr = *(const float4*)(tmr + c);
    float4 xc = *(const float4*)(xxp + c);
    float4 ov, orr;
    ov.x  = rna_tf32(xv.x * mv.x + (1.f - mv.x) * xc.x);
    ov.y  = rna_tf32(xv.y * mv.y + (1.f - mv.y) * xc.y);
    ov.z  = rna_tf32(xv.z * mv.z + (1.f - mv.z) * xc.z);
    ov.w  = rna_tf32(xv.w * mv.w + (1.f - mv.w) * xc.w);
    orr.x = rna_tf32(xv.x * mr.x + (1.f - mr.x) * xc.x);
    orr.y = rna_tf32(xv.y * mr.y + (1.f - mr.y) * xc.y);
    orr.z = rna_tf32(xv.z * mr.z + (1.f - mr.z) * xc.z);
    orr.w = rna_tf32(xv.w * mr.w + (1.f - mr.w) * xc.w);
    *(float4*)(g_xv + i) = ov;
    *(float4*)(g_xr + i) = orr;
}

// ---- t==0 correction: full wkv for the 4 t=0 rows, overwrite g_v.
__global__ void t0_fix_kernel(const float* __restrict__ x,
                              const float* __restrict__ tf,
                              const float* __restrict__ tmk,
                              const float* __restrict__ xxp,
                              const float* __restrict__ aa,
                              const float* __restrict__ bb,
                              const float* __restrict__ pp,
                              const float* __restrict__ wk) {
    const int b    = blockIdx.y;
    const int o    = blockIdx.x * 8 + (threadIdx.x >> 5);
    const int lane = threadIdx.x & 31;
    const float* xrow = x  + (long)b * TDIM * CDIM;
    const float* wrow = wk + (long)o * CDIM;
    float s = 0.f;
    for (int c = lane; c < CDIM; c += 32) {
        float xk = xrow[c] * tmk[c] + (1.f - tmk[c]) * xxp[c];
        s += xk * wrow[c];
    }
    #pragma unroll
    for (int off = 16; off; off >>= 1) s += __shfl_xor_sync(0xffffffffu, s, off);
    if (lane == 0) {
        float ww = tf[o] + s;
        float p  = pp[o];
        float qq = fmaxf(p, ww);
        float e1 = expf(p  - qq);
        float e2 = expf(ww - qq);
        long idx = (long)b * TDIM * NDIM + o;
        float v  = g_v[idx];
        g_v[idx] = (e1 * aa[o] + e2 * v) / (e1 * bb[o] + e2);
    }
}

// ---- tf32 mma.sync GEMM:  C[M,N] = A[M,K] @ W[N,K]^T, tile 128x256
// MODE 0: g_v  = g_xv @ g_wv^T
// MODE 1: g_rv = rna_tf32( sigmoid(g_xr @ g_wr^T) * g_v )
// MODE 2: out  = g_rv @ g_wo^T
template<int MODE>
__global__ void __launch_bounds__(256, 1)
gemm_tf32(float* __restrict__ Cout) {
    const float* __restrict__ A = (MODE == 0) ? g_xv : (MODE == 1) ? g_xr : g_rv;
    const float* __restrict__ W = (MODE == 0) ? g_wv : (MODE == 1) ? g_wr : g_wo;
    float* __restrict__ Cp      = (MODE == 0) ? g_v  : (MODE == 1) ? g_rv : Cout;

    extern __shared__ float sm[];   // [3 stages][A 128x36 | B 256x36]

    const int tid  = threadIdx.x;
    const int lane = tid & 31;
    const int warp = tid >> 5;
    const int wm = warp & 1;          // 2 warps over M (64 rows each)
    const int wn = warp >> 1;         // 4 warps over N (64 cols each)
    const int g  = lane >> 2;
    const int t  = lane & 3;
    const long bm = (long)blockIdx.y * BM;
    const long bn = (long)blockIdx.x * BN;

    float acc[4][8][4];
    #pragma unroll
    for (int i = 0; i < 4; i++)
        #pragma unroll
        for (int j = 0; j < 8; j++)
            #pragma unroll
            for (int k = 0; k < 4; k++) acc[i][j][k] = 0.f;

    const uint32_t sbase = (uint32_t)__cvta_generic_to_shared(sm);

    // cp.async: per stage A = 1024 float4 (4/thread), B = 2048 float4 (8/thread)
    const int srow = tid >> 3;          // 0..31
    const int scol = (tid & 7) * 4;     // floats
    const float* gA = A + (bm + srow) * (long)KDIM + scol;
    const float* gB = W + (bn + srow) * (long)KDIM + scol;
    const uint32_t dOff = (uint32_t)(srow * LSTR + scol) * 4u;

    #define LOAD_STAGE(s, kt) do {                                               \
        uint32_t _a = sbase + (uint32_t)(s) * (STAGE_FLOATS * 4) + dOff;         \
        uint32_t _b = _a + (uint32_t)(MATA_FLOATS * 4);                          \
        int _k = (kt) * BK;                                                      \
        _Pragma("unroll")                                                        \
        for (int _i = 0; _i < 4; _i++)                                           \
            cp16(_a + (uint32_t)(_i * 32 * LSTR * 4), gA + (long)(_i * 32) * KDIM + _k); \
        _Pragma("unroll")                                                        \
        for (int _i = 0; _i < 8; _i++)                                           \
            cp16(_b + (uint32_t)(_i * 32 * LSTR * 4), gB + (long)(_i * 32) * KDIM + _k); \
        asm volatile("cp.async.commit_group;");                                  \
    } while (0)

    LOAD_STAGE(0, 0);
    LOAD_STAGE(1, 1);

    for (int kt = 0; kt < NKT; ++kt) {
        asm volatile("cp.async.wait_group 1;" ::: "memory");
        __syncthreads();
        const int jt = kt + 2;
        if (jt < NKT) { LOAD_STAGE(jt % NSTAGE, jt); }
        else          { asm volatile("cp.async.commit_group;"); }
        const float* As_ = sm + (kt % NSTAGE) * STAGE_FLOATS;
        const float* Bs_ = As_ + MATA_FLOATS;
        #pragma unroll
        for (int ks = 0; ks < 4; ks++) {
            float a[4][4], b[8][2];
            #pragma unroll
            for (int im = 0; im < 4; im++) {
                const float* p = As_ + (wm * 64 + im * 16 + g) * LSTR + ks * 8 + t;
                a[im][0] = p[0];
                a[im][1] = p[8 * LSTR];
                a[im][2] = p[4];
                a[im][3] = p[8 * LSTR + 4];
            }
            #pragma unroll
            for (int in = 0; in < 8; in++) {
                const float* p = Bs_ + (wn * 64 + in * 8 + g) * LSTR + ks * 8 + t;
                b[in][0] = p[0];
                b[in][1] = p[4];
            }
            #pragma unroll
            for (int im = 0; im < 4; im++)
                #pragma unroll
                for (int in = 0; in < 8; in++)
                    asm volatile(
                        "mma.sync.aligned.m16n8k8.row.col.f32.tf32.tf32.f32 "
                        "{%0,%1,%2,%3}, {%4,%5,%6,%7}, {%8,%9}, {%0,%1,%2,%3};"
                        : "+f"(acc[im][in][0]), "+f"(acc[im][in][1]),
                          "+f"(acc[im][in][2]), "+f"(acc[im][in][3])
                        : "r"(__float_as_uint(a[im][0])), "r"(__float_as_uint(a[im][1])),
                          "r"(__float_as_uint(a[im][2])), "r"(__float_as_uint(a[im][3])),
                          "r"(__float_as_uint(b[in][0])), "r"(__float_as_uint(b[in][1])));
        }
        __syncthreads();
    }
    #undef LOAD_STAGE

    // Epilogue
    #pragma unroll
    for (int im = 0; im < 4; im++) {
        const long m0 = bm + wm * 64 + im * 16 + g;
        #pragma unroll
        for (int in = 0; in < 8; in++) {
            const long n0 = bn + wn * 64 + in * 8 + t * 2;
            const long i0 = m0 * NDIM + n0;
            const long i1 = i0 + 8L * NDIM;
            float c0 = acc[im][in][0], c1 = acc[im][in][1];
            float c2 = acc[im][in][2], c3 = acc[im][in][3];
            if (MODE == 1) {
                float2 v0 = *(const float2*)(g_v + i0);
                float2 v1 = *(const float2*)(g_v + i1);
                float r0 = 1.f / (1.f + __expf(-c0));
                float r1 = 1.f / (1.f + __expf(-c1));
                float r2 = 1.f / (1.f + __expf(-c2));
                float r3 = 1.f / (1.f + __expf(-c3));
                *(float2*)(Cp + i0) = make_float2(rna_tf32(r0 * v0.x), rna_tf32(r1 * v0.y));
                *(float2*)(Cp + i1) = make_float2(rna_tf32(r2 * v1.x), rna_tf32(r3 * v1.y));
            } else {
                *(float2*)(Cp + i0) = make_float2(c0, c1);
                *(float2*)(Cp + i1) = make_float2(c2, c3);
            }
        }
    }
}

extern "C" void kernel_launch(void* const* d_in, const int* in_sizes, int n_in,
                              void* d_out, int out_size) {
    (void)in_sizes; (void)n_in; (void)out_size;
    const float* x   = (const float*)d_in[0];
    const float* tf  = (const float*)d_in[1];
    const float* tmk = (const float*)d_in[2];
    const float* tmv = (const float*)d_in[3];
    const float* tmr = (const float*)d_in[4];
    const float* xxp = (const float*)d_in[5];
    const float* aa  = (const float*)d_in[6];
    const float* bb  = (const float*)d_in[7];
    const float* pp  = (const float*)d_in[8];
    const float* wk  = (const float*)d_in[9];
    const float* wv  = (const float*)d_in[10];
    const float* wr  = (const float*)d_in[11];
    const float* wo  = (const float*)d_in[12];
    float* out = (float*)d_out;

    static bool attr_done = false;
    if (!attr_done) {
        cudaFuncSetAttribute(gemm_tf32<0>, cudaFuncAttributeMaxDynamicSharedMemorySize, DYN_SMEM);
        cudaFuncSetAttribute(gemm_tf32<1>, cudaFuncAttributeMaxDynamicSharedMemorySize, DYN_SMEM);
        cudaFuncSetAttribute(gemm_tf32<2>, cudaFuncAttributeMaxDynamicSharedMemorySize, DYN_SMEM);
        attr_done = true;
    }

    prep_w_kernel<<<(unsigned)(((long)NDIM * KDIM) / 1024), 256>>>(wv, wr, wo);
    prep_x_kernel<<<(unsigned)((MDIM * (long)KDIM) / 1024), 256>>>(x, tmv, tmr, xxp);

    dim3 grid((unsigned)(NDIM / BN), (unsigned)(MDIM / BM));   // (8, 64)
    gemm_tf32<0><<<grid, 256, DYN_SMEM>>>(nullptr);            // g_v = xv @ Wv^T
    t0_fix_kernel<<<dim3(CDIM / 8, BDIM), 256>>>(x, tf, tmk, xxp, aa, bb, pp, wk);
    gemm_tf32<1><<<grid, 256, DYN_SMEM>>>(nullptr);            // g_rv = sig(xr@Wr^T)*g_v
    gemm_tf32<2><<<grid, 256, DYN_SMEM>>>(out);                // out = g_rv @ Wo^T
}

// round 10
// speedup vs baseline: 1.1453x; 1.1453x over previous
#include <cuda_runtime.h>
#include <cstdint>

// ---------------------------------------------------------------------------
// TimeMix collapses to: out = (sigmoid(xr @ Wr^T) * (xv @ Wv^T or wkv@t0)) @ Wo^T
// For t>0 padded state is zero so wkv == v; only 4 rows at t==0 need wkv.
// Engine: legacy mma.sync tf32 (tcgen05 unusable: harness targets compute_103).
// R9: CTA 128x128 with 4 warps (warp tile 64x64, LDS/MMA=1.0), 2 CTAs/SM,
//     3-stage cp.async pipeline, single barrier per k-iter.
// ---------------------------------------------------------------------------

namespace {
constexpr int  BDIM = 4;
constexpr int  TDIM = 2048;
constexpr int  CDIM = 2048;
constexpr long MDIM = (long)BDIM * TDIM;   // 8192
constexpr int  KDIM = CDIM;
constexpr int  NDIM = CDIM;

constexpr int BM = 128, BN = 128, BK = 32;
constexpr int NTHREADS = 128;
constexpr int LSTR = 36;                           // padded row stride (floats)
constexpr int MATA_FLOATS  = BM * LSTR;            // 4608
constexpr int MATB_FLOATS  = BN * LSTR;            // 4608
constexpr int STAGE_FLOATS = MATA_FLOATS + MATB_FLOATS;   // 9216
constexpr int NSTAGE = 3;
constexpr int DYN_SMEM = NSTAGE * STAGE_FLOATS * 4;       // 110592
constexpr int NKT = KDIM / BK;                     // 64
}

// Scratch (static device arrays — no cudaMalloc anywhere)
__device__ float g_xv[MDIM * KDIM];
__device__ float g_xr[MDIM * KDIM];
__device__ float g_v [MDIM * NDIM];
__device__ float g_rv[MDIM * NDIM];
__device__ float g_wv[(long)NDIM * KDIM];
__device__ float g_wr[(long)NDIM * KDIM];
__device__ float g_wo[(long)NDIM * KDIM];

__device__ __forceinline__ float rna_tf32(float f) {
    uint32_t u;
    asm("cvt.rna.tf32.f32 %0, %1;" : "=r"(u) : "f"(f));
    return __uint_as_float(u);
}
__device__ __forceinline__ void cp16(uint32_t s, const void* g) {
    asm volatile("cp.async.cg.shared.global [%0], [%1], 16;" :: "r"(s), "l"(g));
}

// ---- round live weights to tf32 (rna removes truncation bias)
__global__ void prep_w_kernel(const float* __restrict__ wv,
                              const float* __restrict__ wr,
                              const float* __restrict__ wo) {
    long i = ((long)blockIdx.x * blockDim.x + threadIdx.x) * 4;
    float4 a = *(const float4*)(wv + i);
    float4 b = *(const float4*)(wr + i);
    float4 c = *(const float4*)(wo + i);
    a.x = rna_tf32(a.x); a.y = rna_tf32(a.y); a.z = rna_tf32(a.z); a.w = rna_tf32(a.w);
    b.x = rna_tf32(b.x); b.y = rna_tf32(b.y); b.z = rna_tf32(b.z); b.w = rna_tf32(b.w);
    c.x = rna_tf32(c.x); c.y = rna_tf32(c.y); c.z = rna_tf32(c.z); c.w = rna_tf32(c.w);
    *(float4*)(g_wv + i) = a;
    *(float4*)(g_wr + i) = b;
    *(float4*)(g_wo + i) = c;
}

// ---- token-mix + tf32 rounding for the two live A-operands
__global__ void prep_x_kernel(const float* __restrict__ x,
                              const float* __restrict__ tmv,
                              const float* __restrict__ tmr,
                              const float* __restrict__ xxp) {
    long i = ((long)blockIdx.x * blockDim.x + threadIdx.x) * 4;
    int  c = (int)(i & (CDIM - 1));
    float4 xv = *(const float4*)(x   + i);
    float4 mv = *(const float4*)(tmv + c);
    float4 mr = *(const float4*)(tmr + c);
    float4 xc = *(const float4*)(xxp + c);
    float4 ov, orr;
    ov.x  = rna_tf32(xv.x * mv.x + (1.f - mv.x) * xc.x);
    ov.y  = rna_tf32(xv.y * mv.y + (1.f - mv.y) * xc.y);
    ov.z  = rna_tf32(xv.z * mv.z + (1.f - mv.z) * xc.z);
    ov.w  = rna_tf32(xv.w * mv.w + (1.f - mv.w) * xc.w);
    orr.x = rna_tf32(xv.x * mr.x + (1.f - mr.x) * xc.x);
    orr.y = rna_tf32(xv.y * mr.y + (1.f - mr.y) * xc.y);
    orr.z = rna_tf32(xv.z * mr.z + (1.f - mr.z) * xc.z);
    orr.w = rna_tf32(xv.w * mr.w + (1.f - mr.w) * xc.w);
    *(float4*)(g_xv + i) = ov;
    *(float4*)(g_xr + i) = orr;
}

// ---- t==0 correction: full wkv for the 4 t=0 rows, overwrite g_v.
__global__ void t0_fix_kernel(const float* __restrict__ x,
                              const float* __restrict__ tf,
                              const float* __restrict__ tmk,
                              const float* __restrict__ xxp,
                              const float* __restrict__ aa,
                              const float* __restrict__ bb,
                              const float* __restrict__ pp,
                              const float* __restrict__ wk) {
    const int b    = blockIdx.y;
    const int o    = blockIdx.x * 8 + (threadIdx.x >> 5);
    const int lane = threadIdx.x & 31;
    const float* xrow = x  + (long)b * TDIM * CDIM;
    const float* wrow = wk + (long)o * CDIM;
    float s = 0.f;
    for (int c = lane; c < CDIM; c += 32) {
        float xk = xrow[c] * tmk[c] + (1.f - tmk[c]) * xxp[c];
        s += xk * wrow[c];
    }
    #pragma unroll
    for (int off = 16; off; off >>= 1) s += __shfl_xor_sync(0xffffffffu, s, off);
    if (lane == 0) {
        float ww = tf[o] + s;
        float p  = pp[o];
        float qq = fmaxf(p, ww);
        float e1 = expf(p  - qq);
        float e2 = expf(ww - qq);
        long idx = (long)b * TDIM * NDIM + o;
        float v  = g_v[idx];
        g_v[idx] = (e1 * aa[o] + e2 * v) / (e1 * bb[o] + e2);
    }
}

// ---- tf32 mma.sync GEMM:  C[M,N] = A[M,K] @ W[N,K]^T, CTA 128x128, 4 warps
// MODE 0: g_v  = g_xv @ g_wv^T
// MODE 1: g_rv = rna_tf32( sigmoid(g_xr @ g_wr^T) * g_v )
// MODE 2: out  = g_rv @ g_wo^T
template<int MODE>
__global__ void __launch_bounds__(NTHREADS, 2)
gemm_tf32(float* __restrict__ Cout) {
    const float* __restrict__ A = (MODE == 0) ? g_xv : (MODE == 1) ? g_xr : g_rv;
    const float* __restrict__ W = (MODE == 0) ? g_wv : (MODE == 1) ? g_wr : g_wo;
    float* __restrict__ Cp      = (MODE == 0) ? g_v  : (MODE == 1) ? g_rv : Cout;

    extern __shared__ float sm[];   // [3 stages][A 128x36 | B 128x36]

    const int tid  = threadIdx.x;
    const int lane = tid & 31;
    const int warp = tid >> 5;
    const int wm = warp & 1;          // 2 warps over M (64 rows each)
    const int wn = warp >> 1;         // 2 warps over N (64 cols each)
    const int g  = lane >> 2;
    const int t  = lane & 3;
    const long bm = (long)blockIdx.y * BM;
    const long bn = (long)blockIdx.x * BN;

    float acc[4][8][4];
    #pragma unroll
    for (int i = 0; i < 4; i++)
        #pragma unroll
        for (int j = 0; j < 8; j++)
            #pragma unroll
            for (int k = 0; k < 4; k++) acc[i][j][k] = 0.f;

    const uint32_t sbase = (uint32_t)__cvta_generic_to_shared(sm);

    // cp.async: per stage A = 1024 float4 -> 8/thread, B same.
    const int srow = tid >> 3;          // 0..15
    const int scol = (tid & 7) * 4;     // floats
    const float* gA = A + (bm + srow) * (long)KDIM + scol;
    const float* gB = W + (bn + srow) * (long)KDIM + scol;
    const uint32_t dOff = (uint32_t)(srow * LSTR + scol) * 4u;

    #define LOAD_STAGE(s, kt) do {                                               \
        uint32_t _a = sbase + (uint32_t)(s) * (STAGE_FLOATS * 4) + dOff;         \
        uint32_t _b = _a + (uint32_t)(MATA_FLOATS * 4);                          \
        int _k = (kt) * BK;                                                      \
        _Pragma("unroll")                                                        \
        for (int _i = 0; _i < 8; _i++) {                                         \
            cp16(_a + (uint32_t)(_i * 16 * LSTR * 4), gA + (long)(_i * 16) * KDIM + _k); \
            cp16(_b + (uint32_t)(_i * 16 * LSTR * 4), gB + (long)(_i * 16) * KDIM + _k); \
        }                                                                        \
        asm volatile("cp.async.commit_group;");                                  \
    } while (0)

    LOAD_STAGE(0, 0);
    LOAD_STAGE(1, 1);

    for (int kt = 0; kt < NKT; ++kt) {
        asm volatile("cp.async.wait_group 1;" ::: "memory");
        __syncthreads();
        const int jt = kt + 2;
        if (jt < NKT) { LOAD_STAGE(jt % NSTAGE, jt); }
        else          { asm volatile("cp.async.commit_group;"); }
        const float* As_ = sm + (kt % NSTAGE) * STAGE_FLOATS;
        const float* Bs_ = As_ + MATA_FLOATS;
        #pragma unroll
        for (int ks = 0; ks < 4; ks++) {
            float a[4][4], b[8][2];
            #pragma unroll
            for (int im = 0; im < 4; im++) {
                const float* p = As_ + (wm * 64 + im * 16 + g) * LSTR + ks * 8 + t;
                a[im][0] = p[0];
                a[im][1] = p[8 * LSTR];
                a[im][2] = p[4];
                a[im][3] = p[8 * LSTR + 4];
            }
            #pragma unroll
            for (int in = 0; in < 8; in++) {
                const float* p = Bs_ + (wn * 64 + in * 8 + g) * LSTR + ks * 8 + t;
                b[in][0] = p[0];
                b[in][1] = p[4];
            }
            #pragma unroll
            for (int im = 0; im < 4; im++)
                #pragma unroll
                for (int in = 0; in < 8; in++)
                    asm volatile(
                        "mma.sync.aligned.m16n8k8.row.col.f32.tf32.tf32.f32 "
                        "{%0,%1,%2,%3}, {%4,%5,%6,%7}, {%8,%9}, {%0,%1,%2,%3};"
                        : "+f"(acc[im][in][0]), "+f"(acc[im][in][1]),
                          "+f"(acc[im][in][2]), "+f"(acc[im][in][3])
                        : "r"(__float_as_uint(a[im][0])), "r"(__float_as_uint(a[im][1])),
                          "r"(__float_as_uint(a[im][2])), "r"(__float_as_uint(a[im][3])),
                          "r"(__float_as_uint(b[in][0])), "r"(__float_as_uint(b[in][1])));
        }
    }
    #undef LOAD_STAGE

    // Epilogue
    #pragma unroll
    for (int im = 0; im < 4; im++) {
        const long m0 = bm + wm * 64 + im * 16 + g;
        #pragma unroll
        for (int in = 0; in < 8; in++) {
            const long n0 = bn + wn * 64 + in * 8 + t * 2;
            const long i0 = m0 * NDIM + n0;
            const long i1 = i0 + 8L * NDIM;
            float c0 = acc[im][in][0], c1 = acc[im][in][1];
            float c2 = acc[im][in][2], c3 = acc[im][in][3];
            if (MODE == 1) {
                float2 v0 = *(const float2*)(g_v + i0);
                float2 v1 = *(const float2*)(g_v + i1);
                float r0 = 1.f / (1.f + __expf(-c0));
                float r1 = 1.f / (1.f + __expf(-c1));
                float r2 = 1.f / (1.f + __expf(-c2));
                float r3 = 1.f / (1.f + __expf(-c3));
                *(float2*)(Cp + i0) = make_float2(rna_tf32(r0 * v0.x), rna_tf32(r1 * v0.y));
                *(float2*)(Cp + i1) = make_float2(rna_tf32(r2 * v1.x), rna_tf32(r3 * v1.y));
            } else {
                *(float2*)(Cp + i0) = make_float2(c0, c1);
                *(float2*)(Cp + i1) = make_float2(c2, c3);
            }
        }
    }
}

extern "C" void kernel_launch(void* const* d_in, const int* in_sizes, int n_in,
                              void* d_out, int out_size) {
    (void)in_sizes; (void)n_in; (void)out_size;
    const float* x   = (const float*)d_in[0];
    const float* tf  = (const float*)d_in[1];
    const float* tmk = (const float*)d_in[2];
    const float* tmv = (const float*)d_in[3];
    const float* tmr = (const float*)d_in[4];
    const float* xxp = (const float*)d_in[5];
    const float* aa  = (const float*)d_in[6];
    const float* bb  = (const float*)d_in[7];
    const float* pp  = (const float*)d_in[8];
    const float* wk  = (const float*)d_in[9];
    const float* wv  = (const float*)d_in[10];
    const float* wr  = (const float*)d_in[11];
    const float* wo  = (const float*)d_in[12];
    float* out = (float*)d_out;

    static bool attr_done = false;
    if (!attr_done) {
        cudaFuncSetAttribute(gemm_tf32<0>, cudaFuncAttributeMaxDynamicSharedMemorySize, DYN_SMEM);
        cudaFuncSetAttribute(gemm_tf32<1>, cudaFuncAttributeMaxDynamicSharedMemorySize, DYN_SMEM);
        cudaFuncSetAttribute(gemm_tf32<2>, cudaFuncAttributeMaxDynamicSharedMemorySize, DYN_SMEM);
        attr_done = true;
    }

    prep_w_kernel<<<(unsigned)(((long)NDIM * KDIM) / 1024), 256>>>(wv, wr, wo);
    prep_x_kernel<<<(unsigned)((MDIM * (long)KDIM) / 1024), 256>>>(x, tmv, tmr, xxp);

    dim3 grid((unsigned)(NDIM / BN), (unsigned)(MDIM / BM));   // (16, 64)
    gemm_tf32<0><<<grid, NTHREADS, DYN_SMEM>>>(nullptr);       // g_v = xv @ Wv^T
    t0_fix_kernel<<<dim3(CDIM / 8, BDIM), 256>>>(x, tf, tmk, xxp, aa, bb, pp, wk);
    gemm_tf32<1><<<grid, NTHREADS, DYN_SMEM>>>(nullptr);       // g_rv = sig(xr@Wr^T)*g_v
    gemm_tf32<2><<<grid, NTHREADS, DYN_SMEM>>>(out);           // out = g_rv @ Wo^T
}

// round 12
// speedup vs baseline: 1.2040x; 1.0513x over previous
#include <cuda_runtime.h>
#include <cstdint>

// ---------------------------------------------------------------------------
// TimeMix collapses to: out = (sigmoid(xr @ Wr^T) * (xv @ Wv^T or wkv@t0)) @ Wo^T
// For t>0 padded state is zero so wkv == v; only 4 rows at t==0 need wkv.
// Engine: legacy mma.sync tf32 (tcgen05 unusable: harness targets compute_103).
// R11 == R10 resubmit (infra failure, kernel never ran): register-fragment
// double buffering in the inner loop to hide LDS->MMA latency.
// ---------------------------------------------------------------------------

namespace {
constexpr int  BDIM = 4;
constexpr int  TDIM = 2048;
constexpr int  CDIM = 2048;
constexpr long MDIM = (long)BDIM * TDIM;   // 8192
constexpr int  KDIM = CDIM;
constexpr int  NDIM = CDIM;

constexpr int BM = 128, BN = 128, BK = 32;
constexpr int NTHREADS = 128;
constexpr int LSTR = 36;                           // padded row stride (floats)
constexpr int MATA_FLOATS  = BM * LSTR;            // 4608
constexpr int MATB_FLOATS  = BN * LSTR;            // 4608
constexpr int STAGE_FLOATS = MATA_FLOATS + MATB_FLOATS;   // 9216
constexpr int NSTAGE = 3;
constexpr int DYN_SMEM = NSTAGE * STAGE_FLOATS * 4;       // 110592
constexpr int NKT = KDIM / BK;                     // 64
}

// Scratch (static device arrays — no cudaMalloc anywhere)
__device__ float g_xv[MDIM * KDIM];
__device__ float g_xr[MDIM * KDIM];
__device__ float g_v [MDIM * NDIM];
__device__ float g_rv[MDIM * NDIM];
__device__ float g_wv[(long)NDIM * KDIM];
__device__ float g_wr[(long)NDIM * KDIM];
__device__ float g_wo[(long)NDIM * KDIM];

__device__ __forceinline__ float rna_tf32(float f) {
    uint32_t u;
    asm("cvt.rna.tf32.f32 %0, %1;" : "=r"(u) : "f"(f));
    return __uint_as_float(u);
}
__device__ __forceinline__ void cp16(uint32_t s, const void* g) {
    asm volatile("cp.async.cg.shared.global [%0], [%1], 16;" :: "r"(s), "l"(g));
}

// ---- round live weights to tf32 (rna removes truncation bias)
__global__ void prep_w_kernel(const float* __restrict__ wv,
                              const float* __restrict__ wr,
                              const float* __restrict__ wo) {
    long i = ((long)blockIdx.x * blockDim.x + threadIdx.x) * 4;
    float4 a = *(const float4*)(wv + i);
    float4 b = *(const float4*)(wr + i);
    float4 c = *(const float4*)(wo + i);
    a.x = rna_tf32(a.x); a.y = rna_tf32(a.y); a.z = rna_tf32(a.z); a.w = rna_tf32(a.w);
    b.x = rna_tf32(b.x); b.y = rna_tf32(b.y); b.z = rna_tf32(b.z); b.w = rna_tf32(b.w);
    c.x = rna_tf32(c.x); c.y = rna_tf32(c.y); c.z = rna_tf32(c.z); c.w = rna_tf32(c.w);
    *(float4*)(g_wv + i) = a;
    *(float4*)(g_wr + i) = b;
    *(float4*)(g_wo + i) = c;
}

// ---- token-mix + tf32 rounding for the two live A-operands
__global__ void prep_x_kernel(const float* __restrict__ x,
                              const float* __restrict__ tmv,
                              const float* __restrict__ tmr,
                              const float* __restrict__ xxp) {
    long i = ((long)blockIdx.x * blockDim.x + threadIdx.x) * 4;
    int  c = (int)(i & (CDIM - 1));
    float4 xv = *(const float4*)(x   + i);
    float4 mv = *(const float4*)(tmv + c);
    float4 mr = *(const float4*)(tmr + c);
    float4 xc = *(const float4*)(xxp + c);
    float4 ov, orr;
    ov.x  = rna_tf32(xv.x * mv.x + (1.f - mv.x) * xc.x);
    ov.y  = rna_tf32(xv.y * mv.y + (1.f - mv.y) * xc.y);
    ov.z  = rna_tf32(xv.z * mv.z + (1.f - mv.z) * xc.z);
    ov.w  = rna_tf32(xv.w * mv.w + (1.f - mv.w) * xc.w);
    orr.x = rna_tf32(xv.x * mr.x + (1.f - mr.x) * xc.x);
    orr.y = rna_tf32(xv.y * mr.y + (1.f - mr.y) * xc.y);
    orr.z = rna_tf32(xv.z * mr.z + (1.f - mr.z) * xc.z);
    orr.w = rna_tf32(xv.w * mr.w + (1.f - mr.w) * xc.w);
    *(float4*)(g_xv + i) = ov;
    *(float4*)(g_xr + i) = orr;
}

// ---- t==0 correction: full wkv for the 4 t=0 rows, overwrite g_v.
__global__ void t0_fix_kernel(const float* __restrict__ x,
                              const float* __restrict__ tf,
                              const float* __restrict__ tmk,
                              const float* __restrict__ xxp,
                              const float* __restrict__ aa,
                              const float* __restrict__ bb,
                              const float* __restrict__ pp,
                              const float* __restrict__ wk) {
    const int b    = blockIdx.y;
    const int o    = blockIdx.x * 8 + (threadIdx.x >> 5);
    const int lane = threadIdx.x & 31;
    const float* xrow = x  + (long)b * TDIM * CDIM;
    const float* wrow = wk + (long)o * CDIM;
    float s = 0.f;
    for (int c = lane; c < CDIM; c += 32) {
        float xk = xrow[c] * tmk[c] + (1.f - tmk[c]) * xxp[c];
        s += xk * wrow[c];
    }
    #pragma unroll
    for (int off = 16; off; off >>= 1) s += __shfl_xor_sync(0xffffffffu, s, off);
    if (lane == 0) {
        float ww = tf[o] + s;
        float p  = pp[o];
        float qq = fmaxf(p, ww);
        float e1 = expf(p  - qq);
        float e2 = expf(ww - qq);
        long idx = (long)b * TDIM * NDIM + o;
        float v  = g_v[idx];
        g_v[idx] = (e1 * aa[o] + e2 * v) / (e1 * bb[o] + e2);
    }
}

// ---- tf32 mma.sync GEMM:  C[M,N] = A[M,K] @ W[N,K]^T, CTA 128x128, 4 warps
// MODE 0: g_v  = g_xv @ g_wv^T
// MODE 1: g_rv = rna_tf32( sigmoid(g_xr @ g_wr^T) * g_v )
// MODE 2: out  = g_rv @ g_wo^T
template<int MODE>
__global__ void __launch_bounds__(NTHREADS, 2)
gemm_tf32(float* __restrict__ Cout) {
    const float* __restrict__ A = (MODE == 0) ? g_xv : (MODE == 1) ? g_xr : g_rv;
    const float* __restrict__ W = (MODE == 0) ? g_wv : (MODE == 1) ? g_wr : g_wo;
    float* __restrict__ Cp      = (MODE == 0) ? g_v  : (MODE == 1) ? g_rv : Cout;

    extern __shared__ float sm[];   // [3 stages][A 128x36 | B 128x36]

    const int tid  = threadIdx.x;
    const int lane = tid & 31;
    const int warp = tid >> 5;
    const int wm = warp & 1;          // 2 warps over M (64 rows each)
    const int wn = warp >> 1;         // 2 warps over N (64 cols each)
    const int g  = lane >> 2;
    const int t  = lane & 3;
    const long bm = (long)blockIdx.y * BM;
    const long bn = (long)blockIdx.x * BN;

    float acc[4][8][4];
    #pragma unroll
    for (int i = 0; i < 4; i++)
        #pragma unroll
        for (int j = 0; j < 8; j++)
            #pragma unroll
            for (int k = 0; k < 4; k++) acc[i][j][k] = 0.f;

    const uint32_t sbase = (uint32_t)__cvta_generic_to_shared(sm);

    // cp.async: per stage A = 1024 float4 -> 8/thread, B same.
    const int srow = tid >> 3;          // 0..15
    const int scol = (tid & 7) * 4;     // floats
    const float* gA = A + (bm + srow) * (long)KDIM + scol;
    const float* gB = W + (bn + srow) * (long)KDIM + scol;
    const uint32_t dOff = (uint32_t)(srow * LSTR + scol) * 4u;

    #define LOAD_STAGE(s, kt) do {                                               \
        uint32_t _a = sbase + (uint32_t)(s) * (STAGE_FLOATS * 4) + dOff;         \
        uint32_t _b = _a + (uint32_t)(MATA_FLOATS * 4);                          \
        int _k = (kt) * BK;                                                      \
        _Pragma("unroll")                                                        \
        for (int _i = 0; _i < 8; _i++) {                                         \
            cp16(_a + (uint32_t)(_i * 16 * LSTR * 4), gA + (long)(_i * 16) * KDIM + _k); \
            cp16(_b + (uint32_t)(_i * 16 * LSTR * 4), gB + (long)(_i * 16) * KDIM + _k); \
        }                                                                        \
        asm volatile("cp.async.commit_group;");                                  \
    } while (0)

    // Fragment load for ks-step into buffer fa/fb
    #define LOAD_FRAGS(fa, fb, As_, Bs_, ks) do {                                \
        _Pragma("unroll")                                                        \
        for (int _im = 0; _im < 4; _im++) {                                      \
            const float* _p = (As_) + (wm * 64 + _im * 16 + g) * LSTR + (ks) * 8 + t; \
            (fa)[_im][0] = _p[0];                                                \
            (fa)[_im][1] = _p[8 * LSTR];                                         \
            (fa)[_im][2] = _p[4];                                                \
            (fa)[_im][3] = _p[8 * LSTR + 4];                                     \
        }                                                                        \
        _Pragma("unroll")                                                        \
        for (int _in = 0; _in < 8; _in++) {                                      \
            const float* _p = (Bs_) + (wn * 64 + _in * 8 + g) * LSTR + (ks) * 8 + t; \
            (fb)[_in][0] = _p[0];                                                \
            (fb)[_in][1] = _p[4];                                                \
        }                                                                        \
    } while (0)

    LOAD_STAGE(0, 0);
    LOAD_STAGE(1, 1);

    float a[2][4][4], b[2][8][2];

    for (int kt = 0; kt < NKT; ++kt) {
        asm volatile("cp.async.wait_group 1;" ::: "memory");
        __syncthreads();
        const float* As_ = sm + (kt % NSTAGE) * STAGE_FLOATS;
        const float* Bs_ = As_ + MATA_FLOATS;
        LOAD_FRAGS(a[0], b[0], As_, Bs_, 0);          // prime ks=0 fragments
        const int jt = kt + 2;
        if (jt < NKT) { LOAD_STAGE(jt % NSTAGE, jt); }
        else          { asm volatile("cp.async.commit_group;"); }
        #pragma unroll
        for (int ks = 0; ks < 4; ks++) {
            const int cur = ks & 1, nxt = cur ^ 1;
            if (ks < 3) LOAD_FRAGS(a[nxt], b[nxt], As_, Bs_, ks + 1);
            #pragma unroll
            for (int im = 0; im < 4; im++)
                #pragma unroll
                for (int in = 0; in < 8; in++)
                    asm volatile(
                        "mma.sync.aligned.m16n8k8.row.col.f32.tf32.tf32.f32 "
                        "{%0,%1,%2,%3}, {%4,%5,%6,%7}, {%8,%9}, {%0,%1,%2,%3};"
                        : "+f"(acc[im][in][0]), "+f"(acc[im][in][1]),
                          "+f"(acc[im][in][2]), "+f"(acc[im][in][3])
                        : "r"(__float_as_uint(a[cur][im][0])), "r"(__float_as_uint(a[cur][im][1])),
                          "r"(__float_as_uint(a[cur][im][2])), "r"(__float_as_uint(a[cur][im][3])),
                          "r"(__float_as_uint(b[cur][in][0])), "r"(__float_as_uint(b[cur][in][1])));
        }
    }
    #undef LOAD_STAGE
    #undef LOAD_FRAGS

    // Epilogue
    #pragma unroll
    for (int im = 0; im < 4; im++) {
        const long m0 = bm + wm * 64 + im * 16 + g;
        #pragma unroll
        for (int in = 0; in < 8; in++) {
            const long n0 = bn + wn * 64 + in * 8 + t * 2;
            const long i0 = m0 * NDIM + n0;
            const long i1 = i0 + 8L * NDIM;
            float c0 = acc[im][in][0], c1 = acc[im][in][1];
            float c2 = acc[im][in][2], c3 = acc[im][in][3];
            if (MODE == 1) {
                float2 v0 = *(const float2*)(g_v + i0);
                float2 v1 = *(const float2*)(g_v + i1);
                float r0 = 1.f / (1.f + __expf(-c0));
                float r1 = 1.f / (1.f + __expf(-c1));
                float r2 = 1.f / (1.f + __expf(-c2));
                float r3 = 1.f / (1.f + __expf(-c3));
                *(float2*)(Cp + i0) = make_float2(rna_tf32(r0 * v0.x), rna_tf32(r1 * v0.y));
                *(float2*)(Cp + i1) = make_float2(rna_tf32(r2 * v1.x), rna_tf32(r3 * v1.y));
            } else {
                *(float2*)(Cp + i0) = make_float2(c0, c1);
                *(float2*)(Cp + i1) = make_float2(c2, c3);
            }
        }
    }
}

extern "C" void kernel_launch(void* const* d_in, const int* in_sizes, int n_in,
                              void* d_out, int out_size) {
    (void)in_sizes; (void)n_in; (void)out_size;
    const float* x   = (const float*)d_in[0];
    const float* tf  = (const float*)d_in[1];
    const float* tmk = (const float*)d_in[2];
    const float* tmv = (const float*)d_in[3];
    const float* tmr = (const float*)d_in[4];
    const float* xxp = (const float*)d_in[5];
    const float* aa  = (const float*)d_in[6];
    const float* bb  = (const float*)d_in[7];
    const float* pp  = (const float*)d_in[8];
    const float* wk  = (const float*)d_in[9];
    const float* wv  = (const float*)d_in[10];
    const float* wr  = (const float*)d_in[11];
    const float* wo  = (const float*)d_in[12];
    float* out = (float*)d_out;

    static bool attr_done = false;
    if (!attr_done) {
        cudaFuncSetAttribute(gemm_tf32<0>, cudaFuncAttributeMaxDynamicSharedMemorySize, DYN_SMEM);
        cudaFuncSetAttribute(gemm_tf32<1>, cudaFuncAttributeMaxDynamicSharedMemorySize, DYN_SMEM);
        cudaFuncSetAttribute(gemm_tf32<2>, cudaFuncAttributeMaxDynamicSharedMemorySize, DYN_SMEM);
        attr_done = true;
    }

    prep_w_kernel<<<(unsigned)(((long)NDIM * KDIM) / 1024), 256>>>(wv, wr, wo);
    prep_x_kernel<<<(unsigned)((MDIM * (long)KDIM) / 1024), 256>>>(x, tmv, tmr, xxp);

    dim3 grid((unsigned)(NDIM / BN), (unsigned)(MDIM / BM));   // (16, 64)
    gemm_tf32<0><<<grid, NTHREADS, DYN_SMEM>>>(nullptr);       // g_v = xv @ Wv^T
    t0_fix_kernel<<<dim3(CDIM / 8, BDIM), 256>>>(x, tf, tmk, xxp, aa, bb, pp, wk);
    gemm_tf32<1><<<grid, NTHREADS, DYN_SMEM>>>(nullptr);       // g_rv = sig(xr@Wr^T)*g_v
    gemm_tf32<2><<<grid, NTHREADS, DYN_SMEM>>>(out);           // out = g_rv @ Wo^T
}